// round 1
// baseline (speedup 1.0000x reference)
#include <cuda_runtime.h>
#include <math.h>

#define P   8192
#define D   128
#define NU  8234
#define NHE 51
#define NUC 42
#define CW  768           // 2 * D * 3 chebyshev width
#define INVTEMP 5.0f

// ---------------- device scratch (static, no allocation) ----------------
__device__ float g_A[P*D];          // col_gate
__device__ float g_B[P*D];          // temp / e ping
__device__ float g_C2[P*D];         // e pong
__device__ float g_acc[P*D];
__device__ float g_hg[P*D];
__device__ float g_z2a[P*D];
__device__ float g_uA[NU*D];        // U_gate
__device__ float g_uB[NU*D];
__device__ float g_uC[NU*D];
__device__ float g_uacc[NU*D];
__device__ float g_ue[NU*D];
__device__ float g_z2b[NU*D];
__device__ float g_hus[NHE*D];      // HG_pu @ e  /  hg_users
__device__ float g_ucl[NUC*D];
__device__ float g_X1r[P*D], g_X1i[P*D], g_X2r[P*D], g_X2i[P*D];
__device__ float g_Tr[(size_t)P*CW], g_Ti[(size_t)P*CW];
__device__ float g_Gr[P*D], g_Gi[P*D];
__device__ float g_fr[P*D], g_fi[P*D];
__device__ float g_fp[P*D];
__device__ float g_SIM[(size_t)NU*NU];
__device__ float g_lr[NU], g_lc[NU], g_dg[NU];
__device__ float g_psum[8*NU];
__device__ float g_tabc[D*D], g_tabs[D*D];
__device__ float g_CrP[CW*D], g_CiP[CW*D];
__device__ float g_br[D], g_bi[D];
__device__ float g_fu[D];
__device__ float g_loss;

// ---------------- generic tiled SGEMM: C = alpha * A @ op(B) (+C) -------
// A: M x K row-major.  transB=0: B is K x N.  transB=1: B is N x K (C=A B^T).
__global__ void sgemm_kernel(const float* __restrict__ A, const float* __restrict__ B,
                             float* __restrict__ C, int M, int N, int K,
                             float alpha, int transB, int accum)
{
    __shared__ __align__(16) float As[16][68];
    __shared__ __align__(16) float Bs[16][68];
    int bm = blockIdx.y * 64, bn = blockIdx.x * 64;
    int t  = threadIdx.x;               // 256 threads
    int ty = t >> 4, tx = t & 15;
    float acc[4][4];
    #pragma unroll
    for (int i = 0; i < 4; i++)
        #pragma unroll
        for (int j = 0; j < 4; j++) acc[i][j] = 0.f;

    for (int k0 = 0; k0 < K; k0 += 16) {
        #pragma unroll
        for (int i = 0; i < 4; i++) {
            int e  = t + i * 256;
            int mm = e >> 4, kk = e & 15;
            int gm = bm + mm, gk = k0 + kk;
            As[kk][mm] = (gm < M && gk < K) ? A[(size_t)gm * K + gk] : 0.f;
        }
        if (!transB) {
            #pragma unroll
            for (int i = 0; i < 4; i++) {
                int e  = t + i * 256;
                int kk = e >> 6, nn = e & 63;
                int gk = k0 + kk, gn = bn + nn;
                Bs[kk][nn] = (gk < K && gn < N) ? B[(size_t)gk * N + gn] : 0.f;
            }
        } else {
            #pragma unroll
            for (int i = 0; i < 4; i++) {
                int e  = t + i * 256;
                int nn = e >> 4, kk = e & 15;
                int gn = bn + nn, gk = k0 + kk;
                Bs[kk][nn] = (gn < N && gk < K) ? B[(size_t)gn * K + gk] : 0.f;
            }
        }
        __syncthreads();
        #pragma unroll
        for (int kk = 0; kk < 16; kk++) {
            float4 av = *(const float4*)&As[kk][ty * 4];
            float4 bv = *(const float4*)&Bs[kk][tx * 4];
            float a4[4] = {av.x, av.y, av.z, av.w};
            float b4[4] = {bv.x, bv.y, bv.z, bv.w};
            #pragma unroll
            for (int i = 0; i < 4; i++)
                #pragma unroll
                for (int j = 0; j < 4; j++) acc[i][j] += a4[i] * b4[j];
        }
        __syncthreads();
    }
    #pragma unroll
    for (int i = 0; i < 4; i++) {
        int gm = bm + ty * 4 + i;
        if (gm >= M) continue;
        #pragma unroll
        for (int j = 0; j < 4; j++) {
            int gn = bn + tx * 4 + j;
            if (gn >= N) continue;
            size_t idx = (size_t)gm * N + gn;
            float v = alpha * acc[i][j];
            C[idx] = accum ? (C[idx] + v) : v;
        }
    }
}

// ---- tall-skinny: C(M x 128) = A(M x K) @ B(K x 128), one block per row ----
__global__ void skinny_mm_k(const float* __restrict__ A, const float* __restrict__ B,
                            float* __restrict__ C, int K)
{
    int m = blockIdx.x;
    int t = threadIdx.x;          // 512
    int n = t & 127;
    int q = t >> 7;               // 0..3
    const float* a = A + (size_t)m * K;
    float s0 = 0.f, s1 = 0.f;
    for (int k = q; k < K; k += 8) {
        s0 += a[k] * B[(size_t)k * 128 + n];
        int k2 = k + 4;
        if (k2 < K) s1 += a[k2] * B[(size_t)k2 * 128 + n];
    }
    __shared__ float sh[3][128];
    float s = s0 + s1;
    if (q) sh[q - 1][n] = s;
    __syncthreads();
    if (q == 0) C[(size_t)m * 128 + n] = s + sh[0][n] + sh[1][n] + sh[2][n];
}

// ---------------- elementwise helpers ----------------
__global__ void copy_k(float* d, const float* s, int n) {
    int i = blockIdx.x * blockDim.x + threadIdx.x;
    if (i < n) d[i] = s[i];
}
__global__ void add_k(float* d, const float* s, int n) {
    int i = blockIdx.x * blockDim.x + threadIdx.x;
    if (i < n) d[i] += s[i];
}
__global__ void gate_k(const float* __restrict__ w, const float* __restrict__ tm,
                       const float* __restrict__ b, float* __restrict__ out, int n) {
    int i = blockIdx.x * blockDim.x + threadIdx.x;
    if (i >= n) return;
    float z = tm[i] + b[i & 127];
    out[i] = w[i] / (1.f + expf(-z));
}
__global__ void kan_gate_k(const float* __restrict__ G, const float* __restrict__ bias,
                           const float* __restrict__ Xa, const float* __restrict__ Xb,
                           float* __restrict__ f, int n) {
    int i = blockIdx.x * blockDim.x + threadIdx.x;
    if (i >= n) return;
    float g = 1.f / (1.f + expf(-(G[i] + bias[i & 127])));
    f[i] = g * Xa[i] + (1.f - g) * Xb[i];
}
__global__ void buildT_k(const float* __restrict__ Xa, const float* __restrict__ Xb,
                         float* __restrict__ T, int n) {   // n = P*D
    int i = blockIdx.x * blockDim.x + threadIdx.x;
    if (i >= n) return;
    int row = i >> 7, c = i & 127;
    float x  = tanhf(Xa[i]);
    float t2 = 2.f * x * x - 1.f;
    float t3 = 2.f * x * t2 - x;
    float* p = T + (size_t)row * CW + c * 3;
    p[0] = x; p[1] = t2; p[2] = t3;
    x  = tanhf(Xb[i]);
    t2 = 2.f * x * x - 1.f;
    t3 = 2.f * x * t2 - x;
    p = T + (size_t)row * CW + 384 + c * 3;
    p[0] = x; p[1] = t2; p[2] = t3;
}

// ---------------- row-wise L2 normalize (D=128, one block/row) ----------------
__global__ void l2norm_k(const float* __restrict__ x, float* __restrict__ y) {
    int r = blockIdx.x, t = threadIdx.x;
    float v = x[(size_t)r * 128 + t];
    __shared__ float sh[128];
    sh[t] = v * v; __syncthreads();
    for (int st = 64; st; st >>= 1) { if (t < st) sh[t] += sh[t + st]; __syncthreads(); }
    y[(size_t)r * 128 + t] = v / fmaxf(sqrtf(sh[0]), 1e-12f);
}
__global__ void addnorm_k(const float* __restrict__ x, const float* __restrict__ ns,
                          float* __restrict__ y) {
    int r = blockIdx.x, t = threadIdx.x;
    float v = x[(size_t)r * 128 + t] + ns[(size_t)r * 128 + t];
    __shared__ float sh[128];
    sh[t] = v * v; __syncthreads();
    for (int st = 64; st; st >>= 1) { if (t < st) sh[t] += sh[t + st]; __syncthreads(); }
    y[(size_t)r * 128 + t] = v / fmaxf(sqrtf(sh[0]), 1e-12f);
}

// ---------------- InfoNCE reductions (|sim| <= 5 so fixed shift of 5) -------
__global__ void row_lse_k(const float* __restrict__ S, float* lse, float* diag, int M) {
    int r = blockIdx.x, t = threadIdx.x;
    const float* row = S + (size_t)r * M;
    float s = 0.f;
    for (int j = t; j < M; j += 128) s += expf(row[j] - 5.0f);
    __shared__ float sh[128];
    sh[t] = s; __syncthreads();
    for (int st = 64; st; st >>= 1) { if (t < st) sh[t] += sh[t + st]; __syncthreads(); }
    if (t == 0) { lse[r] = 5.0f + logf(sh[0]); diag[r] = row[r]; }
}
__global__ void col_part_k(const float* __restrict__ S, int M, int splits) {
    int col = blockIdx.x * 256 + threadIdx.x;
    if (col >= M) return;
    int sp = blockIdx.y;
    long r0 = (long)M * sp / splits, r1 = (long)M * (sp + 1) / splits;
    float s = 0.f;
    for (long r = r0; r < r1; r++) s += expf(S[(size_t)r * M + col] - 5.0f);
    g_psum[sp * NU + col] = s;
}
__global__ void col_comb_k(float* lsec, int M, int splits) {
    int col = blockIdx.x * 256 + threadIdx.x;
    if (col >= M) return;
    float s = 0.f;
    for (int sp = 0; sp < splits; sp++) s += g_psum[sp * NU + col];
    lsec[col] = 5.0f + logf(s);
}
__global__ void nce_accum_k(const float* lr, const float* lc, const float* dg, int M) {
    __shared__ float sh[256];
    int t = threadIdx.x;
    float a = 0.f;
    for (int i = t; i < M; i += 256) a += (lr[i] - dg[i]) + (lc[i] - dg[i]);
    sh[t] = a; __syncthreads();
    for (int st = 128; st; st >>= 1) { if (t < st) sh[t] += sh[t + st]; __syncthreads(); }
    if (t == 0) g_loss += 0.5f * sh[0] / (float)M;
}

// ---------------- setup ----------------
__global__ void setup_tab_k() {
    int i = blockIdx.x * blockDim.x + threadIdx.x;
    if (i >= D * D) return;
    int a = i >> 7, b = i & 127;
    float ang = 6.28318530717958647692f * (float)((a * b) & 127) / 128.f;
    g_tabc[i] = cosf(ang);
    g_tabs[i] = sinf(ang);
}
__global__ void pack_cheb_k(const float* __restrict__ cr, const float* __restrict__ ci) {
    int i = blockIdx.x * blockDim.x + threadIdx.x;
    if (i >= CW * D) return;
    int r = i >> 7, o = i & 127;
    int rr = r % 384;
    int ii = rr / 3, k = rr % 3 + 1;
    g_CrP[i] = cr[((size_t)ii * 128 + o) * 4 + k];
    g_CiP[i] = ci[((size_t)ii * 128 + o) * 4 + k];
}
__global__ void bias_k(const float* __restrict__ cr, const float* __restrict__ ci) {
    int o = threadIdx.x;
    float s1 = 0.f, s2 = 0.f;
    for (int ii = 0; ii < 128; ii++) {
        s1 += cr[((size_t)ii * 128 + o) * 4];
        s2 += ci[((size_t)ii * 128 + o) * 4];
    }
    g_br[o] = 2.f * s1;
    g_bi[o] = 2.f * s2;
    if (o == 0) g_loss = 0.f;
}

// ---------------- finals ----------------
__global__ void finalu_k(const int* __restrict__ uui, const int* __restrict__ ucol) {
    int d = threadIdx.x;
    g_fu[d] = g_ue[(size_t)(*uui) * 128 + d] + g_hus[(size_t)(*ucol) * 128 + d];
}
__global__ void outvec_k(const float* __restrict__ fp, float* __restrict__ out) {
    int gt = blockIdx.x * blockDim.x + threadIdx.x;
    int w = gt >> 5, lane = gt & 31;
    if (w >= P) return;
    const float* row = fp + (size_t)w * 128;
    float s = 0.f;
    #pragma unroll
    for (int d = lane; d < 128; d += 32) s += row[d] * g_fu[d];
    #pragma unroll
    for (int off = 16; off; off >>= 1) s += __shfl_down_sync(0xffffffffu, s, off);
    if (lane == 0) out[w] = s;
}
__global__ void final_k(float* __restrict__ dout, const int* __restrict__ target) {
    __shared__ float sm[1024], ss[1024];
    int t = threadIdx.x;
    float m = -1e30f, s = 0.f;
    for (int j = t; j < P; j += 1024) {
        float x = dout[1 + j];
        float nm = fmaxf(m, x);
        s = s * expf(m - nm) + expf(x - nm);
        m = nm;
    }
    sm[t] = m; ss[t] = s; __syncthreads();
    for (int st = 512; st; st >>= 1) {
        if (t < st) {
            float m2 = sm[t + st], s2 = ss[t + st];
            float nm = fmaxf(sm[t], m2);
            ss[t] = ss[t] * expf(sm[t] - nm) + s2 * expf(m2 - nm);
            sm[t] = nm;
        }
        __syncthreads();
    }
    if (t == 0) {
        float lse = sm[0] + logf(ss[0]);
        dout[0] = (lse - dout[1 + (*target)]) + g_loss;
    }
}

// ---------------- host orchestration ----------------
static void sgemm(const float* A, const float* B, float* C, int M, int N, int K,
                  float alpha, bool transB, bool accum)
{
    dim3 g((N + 63) / 64, (M + 63) / 64);
    sgemm_kernel<<<g, 256>>>(A, B, C, M, N, K, alpha, transB ? 1 : 0, accum ? 1 : 0);
}
static inline dim3 ew(int n) { return dim3((n + 255) / 256); }

#define GSYM(p, s) do { void* _q = nullptr; cudaGetSymbolAddress(&_q, s); p = (float*)_q; } while (0)

extern "C" void kernel_launch(void* const* d_in, const int* in_sizes, int n_in,
                              void* d_out, int out_size)
{
    const float* poi_w    = (const float*)d_in[0];
    const float* ui_w     = (const float*)d_in[1];
    const float* w_gc     = (const float*)d_in[2];
    const float* b_gc     = (const float*)d_in[3];
    const float* w_gU     = (const float*)d_in[4];
    const float* b_gU     = (const float*)d_in[5];
    const float* cheb_r   = (const float*)d_in[6];
    const float* cheb_i   = (const float*)d_in[7];
    const float* HG_pu    = (const float*)d_in[8];
    const float* HG_up    = (const float*)d_in[9];
    const float* U_I      = (const float*)d_in[10];
    const float* noise1   = (const float*)d_in[11];
    const float* noise2   = (const float*)d_in[12];
    const int*   target   = (const int*)d_in[13];
    const int*   user_col = (const int*)d_in[14];
    const int*   user_ui  = (const int*)d_in[15];
    float* out = (float*)d_out;

    float *A, *B, *C2, *acc, *hg, *z2a, *uA, *uB, *uC, *uacc, *ue, *z2b;
    float *hus, *ucl, *X1r, *X1i, *X2r, *X2i, *Tr, *Ti, *Gr, *Gi, *fr, *fi, *fp;
    float *SIM, *lr, *lc, *dg, *tabc, *tabs, *CrP, *CiP;
    GSYM(A, g_A); GSYM(B, g_B); GSYM(C2, g_C2); GSYM(acc, g_acc);
    GSYM(hg, g_hg); GSYM(z2a, g_z2a);
    GSYM(uA, g_uA); GSYM(uB, g_uB); GSYM(uC, g_uC); GSYM(uacc, g_uacc);
    GSYM(ue, g_ue); GSYM(z2b, g_z2b);
    GSYM(hus, g_hus); GSYM(ucl, g_ucl);
    GSYM(X1r, g_X1r); GSYM(X1i, g_X1i); GSYM(X2r, g_X2r); GSYM(X2i, g_X2i);
    GSYM(Tr, g_Tr); GSYM(Ti, g_Ti); GSYM(Gr, g_Gr); GSYM(Gi, g_Gi);
    GSYM(fr, g_fr); GSYM(fi, g_fi); GSYM(fp, g_fp);
    GSYM(SIM, g_SIM); GSYM(lr, g_lr); GSYM(lc, g_lc); GSYM(dg, g_dg);
    GSYM(tabc, g_tabc); GSYM(tabs, g_tabs); GSYM(CrP, g_CrP); GSYM(CiP, g_CiP);

    // setup (also zeroes loss accumulator)
    setup_tab_k<<<ew(D * D), 256>>>();
    pack_cheb_k<<<ew(CW * D), 256>>>(cheb_r, cheb_i);
    bias_k<<<1, 128>>>(cheb_r, cheb_i);

    // gated embeddings
    sgemm(poi_w, w_gc, B, P, D, D, 1.f, false, false);
    gate_k<<<ew(P * D), 256>>>(poi_w, B, b_gc, A, P * D);
    sgemm(ui_w, w_gU, uB, NU, D, D, 1.f, false, false);
    gate_k<<<ew(NU * D), 256>>>(ui_w, uB, b_gU, uA, NU * D);

    // hconv (2 layers) -> hg
    copy_k<<<ew(P * D), 256>>>(acc, A, P * D);
    skinny_mm_k<<<NHE, 512>>>(HG_pu, A, hus, P);
    sgemm(HG_up, hus, B, P, D, NHE, 1.f, false, false);
    add_k<<<ew(P * D), 256>>>(acc, B, P * D);
    skinny_mm_k<<<NHE, 512>>>(HG_pu, B, hus, P);
    sgemm(HG_up, hus, C2, P, D, NHE, 1.f, false, false);
    add_k<<<ew(P * D), 256>>>(acc, C2, P * D);
    l2norm_k<<<P, 128>>>(acc, hg);
    addnorm_k<<<P, 128>>>(hg, noise1, z2a);

    // level_loss = info_nce(hg, hg+noise1)
    sgemm(hg, z2a, SIM, P, P, D, INVTEMP, true, false);
    row_lse_k<<<P, 128>>>(SIM, lr, dg, P);
    { dim3 g((P + 255) / 256, 8); col_part_k<<<g, 256>>>(SIM, P, 8); }
    col_comb_k<<<(P + 255) / 256, 256>>>(lc, P, 8);
    nce_accum_k<<<1, 256>>>(lr, lc, dg, P);

    // hg_users = HG_pu @ hg
    skinny_mm_k<<<NHE, 512>>>(HG_pu, hg, hus, P);

    // gconv (2 layers) -> ue
    copy_k<<<ew(NU * D), 256>>>(uacc, uA, NU * D);
    sgemm(U_I, uA, uB, NU, D, NU, 1.f, false, false);
    add_k<<<ew(NU * D), 256>>>(uacc, uB, NU * D);
    sgemm(U_I, uB, uC, NU, D, NU, 1.f, false, false);
    add_k<<<ew(NU * D), 256>>>(uacc, uC, NU * D);
    l2norm_k<<<NU, 128>>>(uacc, ue);
    addnorm_k<<<NU, 128>>>(ue, noise2, z2b);

    // level_loss1 = info_nce(ue, ue+noise2)
    sgemm(ue, z2b, SIM, NU, NU, D, INVTEMP, true, false);
    row_lse_k<<<NU, 128>>>(SIM, lr, dg, NU);
    { dim3 g((NU + 255) / 256, 8); col_part_k<<<g, 256>>>(SIM, NU, 8); }
    col_comb_k<<<(NU + 255) / 256, 256>>>(lc, NU, 8);
    nce_accum_k<<<1, 256>>>(lr, lc, dg, NU);

    const float* poi_e = ue + (size_t)NUC * D;

    // ssl_p = info_nce(hg, poi_e)
    sgemm(hg, poi_e, SIM, P, P, D, INVTEMP, true, false);
    row_lse_k<<<P, 128>>>(SIM, lr, dg, P);
    { dim3 g((P + 255) / 256, 8); col_part_k<<<g, 256>>>(SIM, P, 8); }
    col_comb_k<<<(P + 255) / 256, 256>>>(lc, P, 8);
    nce_accum_k<<<1, 256>>>(lr, lc, dg, P);

    // ssl = info_nce(user_c = ue[0:42], user_cl = l2norm(hg_users[9:]))
    l2norm_k<<<NUC, 128>>>(hus + 9 * D, ucl);
    sgemm(ue, ucl, SIM, NUC, NUC, D, INVTEMP, true, false);
    row_lse_k<<<NUC, 128>>>(SIM, lr, dg, NUC);
    { dim3 g(1, 1); col_part_k<<<g, 256>>>(SIM, NUC, 1); }
    col_comb_k<<<1, 256>>>(lc, NUC, 1);
    nce_accum_k<<<1, 256>>>(lr, lc, dg, NUC);

    // gated KAN: DFT -> cheby gate -> IDFT
    sgemm(hg, tabc, X1r, P, D, D, 1.f, false, false);
    sgemm(hg, tabs, X1i, P, D, D, -1.f, false, false);
    sgemm(poi_e, tabc, X2r, P, D, D, 1.f, false, false);
    sgemm(poi_e, tabs, X2i, P, D, D, -1.f, false, false);
    buildT_k<<<ew(P * D), 256>>>(X1r, X2r, Tr, P * D);
    buildT_k<<<ew(P * D), 256>>>(X1i, X2i, Ti, P * D);
    sgemm(Tr, CrP, Gr, P, D, CW, 1.f, false, false);
    sgemm(Ti, CiP, Gi, P, D, CW, 1.f, false, false);
    kan_gate_k<<<ew(P * D), 256>>>(Gr, (const float*)0 + 0 == 0 ? Gr : Gr, X1r, X2r, fr, P * D); // placeholder overwritten below
    // (the line above is never what we want; launch proper ones:)
    kan_gate_k<<<ew(P * D), 256>>>(Gr, /*bias*/ nullptr, X1r, X2r, fr, 0); // no-op (n=0)
    {
        float *br, *bi;
        GSYM(br, g_br); GSYM(bi, g_bi);
        kan_gate_k<<<ew(P * D), 256>>>(Gr, br, X1r, X2r, fr, P * D);
        kan_gate_k<<<ew(P * D), 256>>>(Gi, bi, X1i, X2i, fi, P * D);
    }
    sgemm(fr, tabc, fp, P, D, D, 1.f / 128.f, false, false);
    sgemm(fi, tabs, fp, P, D, D, -1.f / 128.f, false, true);

    // final user vector, logits, prediction loss + total loss
    finalu_k<<<1, 128>>>(user_ui, user_col);
    outvec_k<<<(P * 32 + 255) / 256, 256>>>(fp, out + 1);
    final_k<<<1, 1024>>>(out, target);
}

// round 2
// speedup vs baseline: 1.7321x; 1.7321x over previous
#include <cuda_runtime.h>
#include <math.h>

#define P    8192
#define D    128
#define NU   8234
#define NHE  51
#define NUC  42
#define CW   768
#define MPAD 8320
#define NT   65          // max row/col tiles (ceil(8234/128))

// ---------------- device scratch ----------------
__device__ float g_A[P*D];
__device__ float g_B[P*D];
__device__ float g_C2[P*D];
__device__ float g_acc[P*D];
__device__ float g_hg[P*D];
__device__ float g_z2a[P*D];
__device__ float g_uA[NU*D];
__device__ float g_uB[NU*D];
__device__ float g_uC[NU*D];
__device__ float g_uacc[NU*D];
__device__ float g_ue[NU*D];
__device__ float g_z2b[NU*D];
__device__ float g_hus[NHE*D];
__device__ float g_ucl[NUC*D];
__device__ float g_X1r[P*D], g_X1i[P*D], g_X2r[P*D], g_X2i[P*D];
__device__ float g_Tr[(size_t)P*CW], g_Ti[(size_t)P*CW];
__device__ float g_Gr[P*D], g_Gi[P*D];
__device__ float g_fr[P*D], g_fi[P*D];
__device__ float g_fp[P*D];
__device__ float g_part[(size_t)8*MPAD*128];    // split-K partials (34MB)
__device__ float g_rp[(size_t)NT*MPAD];         // row partial exp-sums
__device__ float g_cp[(size_t)NT*MPAD];         // col partial exp-sums
__device__ float g_lr[NU], g_lc[NU], g_dg[NU];
__device__ float g_psum[8*NU];
__device__ float g_tabc[D*D], g_tabs[D*D];
__device__ float g_CrP[CW*D], g_CiP[CW*D];
__device__ float g_br[D], g_bi[D];
__device__ float g_fu[D];
__device__ float g_loss;

// =====================================================================
// Fused InfoNCE tile kernel: S = 5 * Z1 @ Z2^T (K=128), exp(S-5),
// row/col partial sums written per-tile. SIM never materialized.
// grid: (ntiles, ntiles), 256 threads, 128x128 tile, 8x8 microtile.
// =====================================================================
__global__ __launch_bounds__(256, 2)
void nce_fused_k(const float* __restrict__ Z1, const float* __restrict__ Z2,
                 int M, float* __restrict__ rowp, float* __restrict__ colp)
{
    __shared__ __align__(16) float As[16][132];
    __shared__ __align__(16) float Bs[16][132];
    __shared__ __align__(16) float red[128][17];

    int bm = blockIdx.y * 128, bn = blockIdx.x * 128;
    int t = threadIdx.x, tx = t & 15, ty = t >> 4;
    float acc[8][8];
    #pragma unroll
    for (int i = 0; i < 8; i++)
        #pragma unroll
        for (int j = 0; j < 8; j++) acc[i][j] = 0.f;

    #pragma unroll 1
    for (int k0 = 0; k0 < 128; k0 += 16) {
        #pragma unroll
        for (int i = 0; i < 2; i++) {
            int f = t + i * 256;                 // float4 index in [0,512)
            int row = f >> 2, kk = (f & 3) * 4;
            int gm = bm + row;
            float4 v = (gm < M) ? *(const float4*)&Z1[(size_t)gm * 128 + k0 + kk]
                                : make_float4(0.f, 0.f, 0.f, 0.f);
            As[kk + 0][row] = v.x; As[kk + 1][row] = v.y;
            As[kk + 2][row] = v.z; As[kk + 3][row] = v.w;
        }
        #pragma unroll
        for (int i = 0; i < 2; i++) {
            int f = t + i * 256;
            int row = f >> 2, kk = (f & 3) * 4;
            int gn = bn + row;
            float4 v = (gn < M) ? *(const float4*)&Z2[(size_t)gn * 128 + k0 + kk]
                                : make_float4(0.f, 0.f, 0.f, 0.f);
            Bs[kk + 0][row] = v.x; Bs[kk + 1][row] = v.y;
            Bs[kk + 2][row] = v.z; Bs[kk + 3][row] = v.w;
        }
        __syncthreads();
        #pragma unroll
        for (int kk = 0; kk < 16; kk++) {
            float a[8], b[8];
            *(float4*)&a[0] = *(const float4*)&As[kk][ty * 8];
            *(float4*)&a[4] = *(const float4*)&As[kk][ty * 8 + 4];
            *(float4*)&b[0] = *(const float4*)&Bs[kk][tx * 8];
            *(float4*)&b[4] = *(const float4*)&Bs[kk][tx * 8 + 4];
            #pragma unroll
            for (int i = 0; i < 8; i++)
                #pragma unroll
                for (int j = 0; j < 8; j++) acc[i][j] += a[i] * b[j];
        }
        __syncthreads();
    }

    // epilogue: exp + row/col partial sums
    float rs[8], cs[8];
    #pragma unroll
    for (int i = 0; i < 8; i++) { rs[i] = 0.f; cs[i] = 0.f; }
    #pragma unroll
    for (int i = 0; i < 8; i++) {
        int gm = bm + ty * 8 + i;
        #pragma unroll
        for (int j = 0; j < 8; j++) {
            int gn = bn + tx * 8 + j;
            float e = 0.f;
            if (gm < M && gn < M) e = __expf(acc[i][j] * 5.f - 5.f);
            rs[i] += e; cs[j] += e;
        }
    }
    #pragma unroll
    for (int i = 0; i < 8; i++) red[ty * 8 + i][tx] = rs[i];
    __syncthreads();
    if (t < 128) {
        float s = 0.f;
        #pragma unroll
        for (int q = 0; q < 16; q++) s += red[t][q];
        rowp[(size_t)blockIdx.x * MPAD + bm + t] = s;
    }
    __syncthreads();
    #pragma unroll
    for (int j = 0; j < 8; j++) red[tx * 8 + j][ty] = cs[j];
    __syncthreads();
    if (t < 128) {
        float s = 0.f;
        #pragma unroll
        for (int q = 0; q < 16; q++) s += red[t][q];
        colp[(size_t)blockIdx.y * MPAD + bn + t] = s;
    }
}

__global__ void lse_comb_k(const float* __restrict__ pp, int ntiles,
                           float* __restrict__ lse, int M)
{
    int r = blockIdx.x * 256 + threadIdx.x;
    if (r >= M) return;
    float s = 0.f;
    for (int q = 0; q < ntiles; q++) s += pp[(size_t)q * MPAD + r];
    lse[r] = 5.f + logf(s);
}

__global__ void diag_k(const float* __restrict__ Z1, const float* __restrict__ Z2,
                       int M, float* __restrict__ dg)
{
    int gt = blockIdx.x * blockDim.x + threadIdx.x;
    int r = gt >> 5, lane = gt & 31;
    if (r >= M) return;
    const float* a = Z1 + (size_t)r * 128;
    const float* b = Z2 + (size_t)r * 128;
    float s = 0.f;
    #pragma unroll
    for (int d = lane; d < 128; d += 32) s += a[d] * b[d];
    #pragma unroll
    for (int off = 16; off; off >>= 1) s += __shfl_down_sync(0xffffffffu, s, off);
    if (lane == 0) dg[r] = 5.f * s;
}

// =====================================================================
// Split-K GEMM for N=128: Cp[s] = A(MxK) @ B(Kx128) over K-slice s.
// grid: (S, mtiles). Requires K even. Partials combined by comb_n128_k.
// =====================================================================
__global__ __launch_bounds__(256, 2)
void gemm_n128_k(const float* __restrict__ A, const float* __restrict__ B,
                 float* __restrict__ Cp, int M, int K, int Kc)
{
    __shared__ __align__(16) float As[16][132];
    __shared__ __align__(16) float Bs[16][132];
    int s = blockIdx.x;
    int bm = blockIdx.y * 128;
    int kb = s * Kc;
    int ke = min(K, kb + Kc);
    int t = threadIdx.x, tx = t & 15, ty = t >> 4;
    float acc[8][8];
    #pragma unroll
    for (int i = 0; i < 8; i++)
        #pragma unroll
        for (int j = 0; j < 8; j++) acc[i][j] = 0.f;

    for (int k0 = kb; k0 < ke; k0 += 16) {
        #pragma unroll
        for (int i = 0; i < 4; i++) {
            int f = t + i * 256;                 // float2 index in [0,1024)
            int row = f >> 3, kk = (f & 7) * 2;
            int gm = bm + row, gk = k0 + kk;
            float2 v = (gm < M && gk < ke) ? *(const float2*)&A[(size_t)gm * K + gk]
                                           : make_float2(0.f, 0.f);
            As[kk][row] = v.x; As[kk + 1][row] = v.y;
        }
        #pragma unroll
        for (int i = 0; i < 2; i++) {
            int f = t + i * 256;                 // float4 index in [0,512)
            int kk = f >> 5, n4 = (f & 31) * 4;
            int gk = k0 + kk;
            float4 v = (gk < ke) ? *(const float4*)&B[(size_t)gk * 128 + n4]
                                 : make_float4(0.f, 0.f, 0.f, 0.f);
            *(float4*)&Bs[kk][n4] = v;
        }
        __syncthreads();
        #pragma unroll
        for (int kk = 0; kk < 16; kk++) {
            float a[8], b[8];
            *(float4*)&a[0] = *(const float4*)&As[kk][ty * 8];
            *(float4*)&a[4] = *(const float4*)&As[kk][ty * 8 + 4];
            *(float4*)&b[0] = *(const float4*)&Bs[kk][tx * 8];
            *(float4*)&b[4] = *(const float4*)&Bs[kk][tx * 8 + 4];
            #pragma unroll
            for (int i = 0; i < 8; i++)
                #pragma unroll
                for (int j = 0; j < 8; j++) acc[i][j] += a[i] * b[j];
        }
        __syncthreads();
    }
    size_t base = (size_t)s * ((size_t)MPAD * 128);
    #pragma unroll
    for (int i = 0; i < 8; i++) {
        int gm = bm + ty * 8 + i;
        if (gm >= M) continue;
        *(float4*)&Cp[base + (size_t)gm * 128 + tx * 8]     = *(float4*)&acc[i][0];
        *(float4*)&Cp[base + (size_t)gm * 128 + tx * 8 + 4] = *(float4*)&acc[i][4];
    }
}

__global__ void comb_n128_k(const float* __restrict__ Cp, int S,
                            float* __restrict__ C, int M, float alpha, int accum)
{
    int i = blockIdx.x * 256 + threadIdx.x;
    if (i >= M * 128) return;
    float s = 0.f;
    for (int q = 0; q < S; q++) s += Cp[(size_t)q * ((size_t)MPAD * 128) + i];
    float v = alpha * s;
    C[i] = accum ? C[i] + v : v;
}

// =====================================================================
// generic tiled SGEMM (small/odd-K cases only)
// =====================================================================
__global__ void sgemm_kernel(const float* __restrict__ A, const float* __restrict__ B,
                             float* __restrict__ C, int M, int N, int K,
                             float alpha, int transB, int accum)
{
    __shared__ __align__(16) float As[16][68];
    __shared__ __align__(16) float Bs[16][68];
    int bm = blockIdx.y * 64, bn = blockIdx.x * 64;
    int t  = threadIdx.x;
    int ty = t >> 4, tx = t & 15;
    float acc[4][4];
    #pragma unroll
    for (int i = 0; i < 4; i++)
        #pragma unroll
        for (int j = 0; j < 4; j++) acc[i][j] = 0.f;

    for (int k0 = 0; k0 < K; k0 += 16) {
        #pragma unroll
        for (int i = 0; i < 4; i++) {
            int e  = t + i * 256;
            int mm = e >> 4, kk = e & 15;
            int gm = bm + mm, gk = k0 + kk;
            As[kk][mm] = (gm < M && gk < K) ? A[(size_t)gm * K + gk] : 0.f;
        }
        if (!transB) {
            #pragma unroll
            for (int i = 0; i < 4; i++) {
                int e  = t + i * 256;
                int kk = e >> 6, nn = e & 63;
                int gk = k0 + kk, gn = bn + nn;
                Bs[kk][nn] = (gk < K && gn < N) ? B[(size_t)gk * N + gn] : 0.f;
            }
        } else {
            #pragma unroll
            for (int i = 0; i < 4; i++) {
                int e  = t + i * 256;
                int nn = e >> 4, kk = e & 15;
                int gn = bn + nn, gk = k0 + kk;
                Bs[kk][nn] = (gn < N && gk < K) ? B[(size_t)gn * K + gk] : 0.f;
            }
        }
        __syncthreads();
        #pragma unroll
        for (int kk = 0; kk < 16; kk++) {
            float4 av = *(const float4*)&As[kk][ty * 4];
            float4 bv = *(const float4*)&Bs[kk][tx * 4];
            float a4[4] = {av.x, av.y, av.z, av.w};
            float b4[4] = {bv.x, bv.y, bv.z, bv.w};
            #pragma unroll
            for (int i = 0; i < 4; i++)
                #pragma unroll
                for (int j = 0; j < 4; j++) acc[i][j] += a4[i] * b4[j];
        }
        __syncthreads();
    }
    #pragma unroll
    for (int i = 0; i < 4; i++) {
        int gm = bm + ty * 4 + i;
        if (gm >= M) continue;
        #pragma unroll
        for (int j = 0; j < 4; j++) {
            int gn = bn + tx * 4 + j;
            if (gn >= N) continue;
            size_t idx = (size_t)gm * N + gn;
            float v = alpha * acc[i][j];
            C[idx] = accum ? (C[idx] + v) : v;
        }
    }
}

// ---- tall-skinny: C(NHE x 128) = A(NHE x K) @ B(K x 128) ----
__global__ void skinny_mm_k(const float* __restrict__ A, const float* __restrict__ B,
                            float* __restrict__ C, int K)
{
    int m = blockIdx.x;
    int t = threadIdx.x;
    int n = t & 127;
    int q = t >> 7;
    const float* a = A + (size_t)m * K;
    float s0 = 0.f, s1 = 0.f;
    for (int k = q; k < K; k += 8) {
        s0 += a[k] * B[(size_t)k * 128 + n];
        int k2 = k + 4;
        if (k2 < K) s1 += a[k2] * B[(size_t)k2 * 128 + n];
    }
    __shared__ float sh[3][128];
    float s = s0 + s1;
    if (q) sh[q - 1][n] = s;
    __syncthreads();
    if (q == 0) C[(size_t)m * 128 + n] = s + sh[0][n] + sh[1][n] + sh[2][n];
}

// ---------------- elementwise ----------------
__global__ void copy_k(float* d, const float* s, int n) {
    int i = blockIdx.x * blockDim.x + threadIdx.x;
    if (i < n) d[i] = s[i];
}
__global__ void add_k(float* d, const float* s, int n) {
    int i = blockIdx.x * blockDim.x + threadIdx.x;
    if (i < n) d[i] += s[i];
}
__global__ void gate_k(const float* __restrict__ w, const float* __restrict__ tm,
                       const float* __restrict__ b, float* __restrict__ out, int n) {
    int i = blockIdx.x * blockDim.x + threadIdx.x;
    if (i >= n) return;
    float z = tm[i] + b[i & 127];
    out[i] = w[i] / (1.f + expf(-z));
}
__global__ void kan_gate_k(const float* __restrict__ G, const float* __restrict__ bias,
                           const float* __restrict__ Xa, const float* __restrict__ Xb,
                           float* __restrict__ f, int n) {
    int i = blockIdx.x * blockDim.x + threadIdx.x;
    if (i >= n) return;
    float g = 1.f / (1.f + expf(-(G[i] + bias[i & 127])));
    f[i] = g * Xa[i] + (1.f - g) * Xb[i];
}
__global__ void buildT_k(const float* __restrict__ Xa, const float* __restrict__ Xb,
                         float* __restrict__ T, int n) {
    int i = blockIdx.x * blockDim.x + threadIdx.x;
    if (i >= n) return;
    int row = i >> 7, c = i & 127;
    float x  = tanhf(Xa[i]);
    float t2 = 2.f * x * x - 1.f;
    float t3 = 2.f * x * t2 - x;
    float* p = T + (size_t)row * CW + c * 3;
    p[0] = x; p[1] = t2; p[2] = t3;
    x  = tanhf(Xb[i]);
    t2 = 2.f * x * x - 1.f;
    t3 = 2.f * x * t2 - x;
    p = T + (size_t)row * CW + 384 + c * 3;
    p[0] = x; p[1] = t2; p[2] = t3;
}

// ---------------- L2 normalize ----------------
__global__ void l2norm_k(const float* __restrict__ x, float* __restrict__ y) {
    int r = blockIdx.x, t = threadIdx.x;
    float v = x[(size_t)r * 128 + t];
    __shared__ float sh[128];
    sh[t] = v * v; __syncthreads();
    for (int st = 64; st; st >>= 1) { if (t < st) sh[t] += sh[t + st]; __syncthreads(); }
    y[(size_t)r * 128 + t] = v / fmaxf(sqrtf(sh[0]), 1e-12f);
}
__global__ void addnorm_k(const float* __restrict__ x, const float* __restrict__ ns,
                          float* __restrict__ y) {
    int r = blockIdx.x, t = threadIdx.x;
    float v = x[(size_t)r * 128 + t] + ns[(size_t)r * 128 + t];
    __shared__ float sh[128];
    sh[t] = v * v; __syncthreads();
    for (int st = 64; st; st >>= 1) { if (t < st) sh[t] += sh[t + st]; __syncthreads(); }
    y[(size_t)r * 128 + t] = v / fmaxf(sqrtf(sh[0]), 1e-12f);
}

// ---------------- small InfoNCE path (NUC only) ----------------
__global__ void row_lse_k(const float* __restrict__ S, float* lse, float* diag, int M) {
    int r = blockIdx.x, t = threadIdx.x;
    const float* row = S + (size_t)r * M;
    float s = 0.f;
    for (int j = t; j < M; j += 128) s += expf(row[j] - 5.0f);
    __shared__ float sh[128];
    sh[t] = s; __syncthreads();
    for (int st = 64; st; st >>= 1) { if (t < st) sh[t] += sh[t + st]; __syncthreads(); }
    if (t == 0) { lse[r] = 5.0f + logf(sh[0]); diag[r] = row[r]; }
}
__global__ void col_part_k(const float* __restrict__ S, int M, int splits) {
    int col = blockIdx.x * 256 + threadIdx.x;
    if (col >= M) return;
    int sp = blockIdx.y;
    long r0 = (long)M * sp / splits, r1 = (long)M * (sp + 1) / splits;
    float s = 0.f;
    for (long r = r0; r < r1; r++) s += expf(S[(size_t)r * M + col] - 5.0f);
    g_psum[sp * NU + col] = s;
}
__global__ void col_comb_k(float* lsec, int M, int splits) {
    int col = blockIdx.x * 256 + threadIdx.x;
    if (col >= M) return;
    float s = 0.f;
    for (int sp = 0; sp < splits; sp++) s += g_psum[sp * NU + col];
    lsec[col] = 5.0f + logf(s);
}
__global__ void nce_accum_k(const float* lr, const float* lc, const float* dg, int M) {
    __shared__ float sh[256];
    int t = threadIdx.x;
    float a = 0.f;
    for (int i = t; i < M; i += 256) a += (lr[i] - dg[i]) + (lc[i] - dg[i]);
    sh[t] = a; __syncthreads();
    for (int st = 128; st; st >>= 1) { if (t < st) sh[t] += sh[t + st]; __syncthreads(); }
    if (t == 0) g_loss += 0.5f * sh[0] / (float)M;
}

// ---------------- setup ----------------
__global__ void setup_tab_k() {
    int i = blockIdx.x * blockDim.x + threadIdx.x;
    if (i >= D * D) return;
    int a = i >> 7, b = i & 127;
    float ang = 6.28318530717958647692f * (float)((a * b) & 127) / 128.f;
    g_tabc[i] = cosf(ang);
    g_tabs[i] = sinf(ang);
}
__global__ void pack_cheb_k(const float* __restrict__ cr, const float* __restrict__ ci) {
    int i = blockIdx.x * blockDim.x + threadIdx.x;
    if (i >= CW * D) return;
    int r = i >> 7, o = i & 127;
    int rr = r % 384;
    int ii = rr / 3, k = rr % 3 + 1;
    g_CrP[i] = cr[((size_t)ii * 128 + o) * 4 + k];
    g_CiP[i] = ci[((size_t)ii * 128 + o) * 4 + k];
}
__global__ void bias_k(const float* __restrict__ cr, const float* __restrict__ ci) {
    int o = threadIdx.x;
    float s1 = 0.f, s2 = 0.f;
    for (int ii = 0; ii < 128; ii++) {
        s1 += cr[((size_t)ii * 128 + o) * 4];
        s2 += ci[((size_t)ii * 128 + o) * 4];
    }
    g_br[o] = 2.f * s1;
    g_bi[o] = 2.f * s2;
    if (o == 0) g_loss = 0.f;
}

// ---------------- finals ----------------
__global__ void finalu_k(const int* __restrict__ uui, const int* __restrict__ ucol) {
    int d = threadIdx.x;
    g_fu[d] = g_ue[(size_t)(*uui) * 128 + d] + g_hus[(size_t)(*ucol) * 128 + d];
}
__global__ void outvec_k(const float* __restrict__ fp, float* __restrict__ out) {
    int gt = blockIdx.x * blockDim.x + threadIdx.x;
    int w = gt >> 5, lane = gt & 31;
    if (w >= P) return;
    const float* row = fp + (size_t)w * 128;
    float s = 0.f;
    #pragma unroll
    for (int d = lane; d < 128; d += 32) s += row[d] * g_fu[d];
    #pragma unroll
    for (int off = 16; off; off >>= 1) s += __shfl_down_sync(0xffffffffu, s, off);
    if (lane == 0) out[w] = s;
}
__global__ void final_k(float* __restrict__ dout, const int* __restrict__ target) {
    __shared__ float sm[1024], ss[1024];
    int t = threadIdx.x;
    float m = -1e30f, s = 0.f;
    for (int j = t; j < P; j += 1024) {
        float x = dout[1 + j];
        float nm = fmaxf(m, x);
        s = s * expf(m - nm) + expf(x - nm);
        m = nm;
    }
    sm[t] = m; ss[t] = s; __syncthreads();
    for (int st = 512; st; st >>= 1) {
        if (t < st) {
            float m2 = sm[t + st], s2 = ss[t + st];
            float nm = fmaxf(sm[t], m2);
            ss[t] = ss[t] * expf(sm[t] - nm) + s2 * expf(m2 - nm);
            sm[t] = nm;
        }
        __syncthreads();
    }
    if (t == 0) {
        float lse = sm[0] + logf(ss[0]);
        dout[0] = (lse - dout[1 + (*target)]) + g_loss;
    }
}

// ---------------- host orchestration ----------------
static inline dim3 ew(int n) { return dim3((n + 255) / 256); }

#define GSYM(p, s) do { void* _q = nullptr; cudaGetSymbolAddress(&_q, s); p = (float*)_q; } while (0)

static float *s_part;

static void gemm128(const float* A, const float* B, float* C, int M, int K, int S,
                    float alpha, bool accum)
{
    int Kc = (((K + S - 1) / S) + 1) & ~1;
    dim3 g(S, (M + 127) / 128);
    gemm_n128_k<<<g, 256>>>(A, B, s_part, M, K, Kc);
    comb_n128_k<<<ew(M * 128), 256>>>(s_part, S, C, M, alpha, accum ? 1 : 0);
}

static void run_nce(const float* Z1, const float* Z2, int M,
                    float* rp, float* cp, float* lr, float* lc, float* dg)
{
    int nt = (M + 127) / 128;
    dim3 g(nt, nt);
    nce_fused_k<<<g, 256>>>(Z1, Z2, M, rp, cp);
    lse_comb_k<<<ew(M), 256>>>(rp, nt, lr, M);
    lse_comb_k<<<ew(M), 256>>>(cp, nt, lc, M);
    diag_k<<<(M * 32 + 255) / 256, 256>>>(Z1, Z2, M, dg);
    nce_accum_k<<<1, 256>>>(lr, lc, dg, M);
}

extern "C" void kernel_launch(void* const* d_in, const int* in_sizes, int n_in,
                              void* d_out, int out_size)
{
    const float* poi_w    = (const float*)d_in[0];
    const float* ui_w     = (const float*)d_in[1];
    const float* w_gc     = (const float*)d_in[2];
    const float* b_gc     = (const float*)d_in[3];
    const float* w_gU     = (const float*)d_in[4];
    const float* b_gU     = (const float*)d_in[5];
    const float* cheb_r   = (const float*)d_in[6];
    const float* cheb_i   = (const float*)d_in[7];
    const float* HG_pu    = (const float*)d_in[8];
    const float* HG_up    = (const float*)d_in[9];
    const float* U_I      = (const float*)d_in[10];
    const float* noise1   = (const float*)d_in[11];
    const float* noise2   = (const float*)d_in[12];
    const int*   target   = (const int*)d_in[13];
    const int*   user_col = (const int*)d_in[14];
    const int*   user_ui  = (const int*)d_in[15];
    float* out = (float*)d_out;

    float *A, *B, *C2, *acc, *hg, *z2a, *uA, *uB, *uC, *uacc, *ue, *z2b;
    float *hus, *ucl, *X1r, *X1i, *X2r, *X2i, *Tr, *Ti, *Gr, *Gi, *fr, *fi, *fp;
    float *lr, *lc, *dg, *tabc, *tabs, *CrP, *CiP, *br, *bi, *rp, *cp;
    GSYM(A, g_A); GSYM(B, g_B); GSYM(C2, g_C2); GSYM(acc, g_acc);
    GSYM(hg, g_hg); GSYM(z2a, g_z2a);
    GSYM(uA, g_uA); GSYM(uB, g_uB); GSYM(uC, g_uC); GSYM(uacc, g_uacc);
    GSYM(ue, g_ue); GSYM(z2b, g_z2b);
    GSYM(hus, g_hus); GSYM(ucl, g_ucl);
    GSYM(X1r, g_X1r); GSYM(X1i, g_X1i); GSYM(X2r, g_X2r); GSYM(X2i, g_X2i);
    GSYM(Tr, g_Tr); GSYM(Ti, g_Ti); GSYM(Gr, g_Gr); GSYM(Gi, g_Gi);
    GSYM(fr, g_fr); GSYM(fi, g_fi); GSYM(fp, g_fp);
    GSYM(lr, g_lr); GSYM(lc, g_lc); GSYM(dg, g_dg);
    GSYM(tabc, g_tabc); GSYM(tabs, g_tabs); GSYM(CrP, g_CrP); GSYM(CiP, g_CiP);
    GSYM(br, g_br); GSYM(bi, g_bi); GSYM(rp, g_rp); GSYM(cp, g_cp);
    GSYM(s_part, g_part);

    // setup (also zeroes loss accumulator)
    setup_tab_k<<<ew(D * D), 256>>>();
    pack_cheb_k<<<ew(CW * D), 256>>>(cheb_r, cheb_i);
    bias_k<<<1, 128>>>(cheb_r, cheb_i);

    // gated embeddings
    gemm128(poi_w, w_gc, B, P, 128, 4, 1.f, false);
    gate_k<<<ew(P * D), 256>>>(poi_w, B, b_gc, A, P * D);
    gemm128(ui_w, w_gU, uB, NU, 128, 4, 1.f, false);
    gate_k<<<ew(NU * D), 256>>>(ui_w, uB, b_gU, uA, NU * D);

    // hconv (2 layers) -> hg
    copy_k<<<ew(P * D), 256>>>(acc, A, P * D);
    skinny_mm_k<<<NHE, 512>>>(HG_pu, A, hus, P);
    { dim3 g(2, 128); sgemm_kernel<<<g, 256>>>(HG_up, hus, B, P, 128, NHE, 1.f, 0, 0); }
    add_k<<<ew(P * D), 256>>>(acc, B, P * D);
    skinny_mm_k<<<NHE, 512>>>(HG_pu, B, hus, P);
    { dim3 g(2, 128); sgemm_kernel<<<g, 256>>>(HG_up, hus, C2, P, 128, NHE, 1.f, 0, 0); }
    add_k<<<ew(P * D), 256>>>(acc, C2, P * D);
    l2norm_k<<<P, 128>>>(acc, hg);
    addnorm_k<<<P, 128>>>(hg, noise1, z2a);

    // level_loss = info_nce(hg, hg+noise1)
    run_nce(hg, z2a, P, rp, cp, lr, lc, dg);

    // hg_users
    skinny_mm_k<<<NHE, 512>>>(HG_pu, hg, hus, P);

    // gconv (2 layers) -> ue
    copy_k<<<ew(NU * D), 256>>>(uacc, uA, NU * D);
    gemm128(U_I, uA, uB, NU, NU, 8, 1.f, false);
    add_k<<<ew(NU * D), 256>>>(uacc, uB, NU * D);
    gemm128(U_I, uB, uC, NU, NU, 8, 1.f, false);
    add_k<<<ew(NU * D), 256>>>(uacc, uC, NU * D);
    l2norm_k<<<NU, 128>>>(uacc, ue);
    addnorm_k<<<NU, 128>>>(ue, noise2, z2b);

    // level_loss1 = info_nce(ue, ue+noise2)
    run_nce(ue, z2b, NU, rp, cp, lr, lc, dg);

    const float* poi_e = ue + (size_t)NUC * D;

    // ssl_p = info_nce(hg, poi_e)
    run_nce(hg, poi_e, P, rp, cp, lr, lc, dg);

    // ssl = info_nce(ue[0:42], l2norm(hg_users[9:]))  (small path)
    l2norm_k<<<NUC, 128>>>(hus + 9 * D, ucl);
    { dim3 g(1, 1); sgemm_kernel<<<g, 256>>>(ue, ucl, s_part, NUC, NUC, 128, 5.f, 1, 0); }
    row_lse_k<<<NUC, 128>>>(s_part, lr, dg, NUC);
    { dim3 g(1, 1); col_part_k<<<g, 256>>>(s_part, NUC, 1); }
    col_comb_k<<<1, 256>>>(lc, NUC, 1);
    nce_accum_k<<<1, 256>>>(lr, lc, dg, NUC);

    // gated KAN: DFT -> cheby gate -> IDFT
    gemm128(hg, tabc, X1r, P, 128, 4,  1.f, false);
    gemm128(hg, tabs, X1i, P, 128, 4, -1.f, false);
    gemm128(poi_e, tabc, X2r, P, 128, 4,  1.f, false);
    gemm128(poi_e, tabs, X2i, P, 128, 4, -1.f, false);
    buildT_k<<<ew(P * D), 256>>>(X1r, X2r, Tr, P * D);
    buildT_k<<<ew(P * D), 256>>>(X1i, X2i, Ti, P * D);
    gemm128(Tr, CrP, Gr, P, CW, 4, 1.f, false);
    gemm128(Ti, CiP, Gi, P, CW, 4, 1.f, false);
    kan_gate_k<<<ew(P * D), 256>>>(Gr, br, X1r, X2r, fr, P * D);
    kan_gate_k<<<ew(P * D), 256>>>(Gi, bi, X1i, X2i, fi, P * D);
    gemm128(fr, tabc, fp, P, 128, 4,  1.f / 128.f, false);
    gemm128(fi, tabs, fp, P, 128, 4, -1.f / 128.f, true);

    // final user vector, logits, loss
    finalu_k<<<1, 128>>>(user_ui, user_col);
    outvec_k<<<(P * 32 + 255) / 256, 256>>>(fp, out + 1);
    final_k<<<1, 1024>>>(out, target);
}